// round 4
// baseline (speedup 1.0000x reference)
#include <cuda_runtime.h>
#include <cuda_bf16.h>
#include <cstdint>
#include <cstdio>

// Problem constants
#define BB 2
#define TT 2048
#define DD 768
#define HH 12
#define HS 64
#define FF 3072
#define HALF 1536
#define ROWS (BB*TT)          // 4096

// ---------------- device scratch (no allocations allowed) ----------------
__device__ float g_h   [ROWS * DD];        // rmsnorm output (reused for h2)
__device__ float g_wqkv[DD * 3 * DD];      // packed QKV weight [768][2304]
__device__ float g_qkv [ROWS * 3 * DD];    // Q|K|V  [4096][2304]
__device__ float g_attn[ROWS * DD];        // attention output (heads concat)
__device__ float g_x1  [ROWS * DD];        // x + attn proj residual
__device__ float g_u   [ROWS * FF];        // FFN hidden
__device__ float g_gsw [ROWS * HALF];      // silu(gate)*a

// ---------------- pack Wq,Wk,Wv -> [d][which*768 + h*64 + k] ----------------
__global__ void pack_wqkv_kernel(const float* __restrict__ Wq,
                                 const float* __restrict__ Wk,
                                 const float* __restrict__ Wv) {
    int idx = blockIdx.x * 256 + threadIdx.x;
    if (idx >= DD * 3 * DD) return;
    int d   = idx / (3 * DD);
    int col = idx % (3 * DD);
    int which = col / DD;
    int rem   = col % DD;
    int h = rem / HS, k = rem % HS;
    const float* src = (which == 0) ? Wq : (which == 1) ? Wk : Wv;
    g_wqkv[idx] = src[(size_t)h * DD * HS + (size_t)d * HS + k];
}

// ---------------- RMSNorm (p=-1 style): y = g * x / (rms + eps) ----------------
__global__ void rmsnorm_kernel(const float* __restrict__ X,
                               const float* __restrict__ g,
                               float* __restrict__ Y) {
    int row = blockIdx.x;
    const float* x = X + (size_t)row * DD;
    float* y = Y + (size_t)row * DD;
    __shared__ float red[256];
    int t = threadIdx.x;
    float ss = 0.f;
    #pragma unroll
    for (int i = t; i < DD; i += 256) { float v = x[i]; ss += v * v; }
    red[t] = ss; __syncthreads();
    #pragma unroll
    for (int s2 = 128; s2 > 0; s2 >>= 1) {
        if (t < s2) red[t] += red[t + s2];
        __syncthreads();
    }
    float rms = sqrtf(red[0] * (1.0f / DD));
    float inv = 1.0f / (rms + 1e-8f);
    #pragma unroll
    for (int i = t; i < DD; i += 256) y[i] = g[i] * x[i] * inv;
}

// ---------------- tiled SGEMM: C = A[M,K] @ B[K,N] (+bias)(+res) ----------------
#define BM 128
#define BN 128
#define BK 16
#define TM 8
#define TN 8

__global__ __launch_bounds__(256)
void gemm_kernel(const float* __restrict__ A, const float* __restrict__ B,
                 float* __restrict__ C,
                 const float* __restrict__ bias, const float* __restrict__ res,
                 int M, int N, int K) {
    __shared__ float As[BK][BM];
    __shared__ float Bs[BK][BN];
    int tid = threadIdx.x;
    int block_row = blockIdx.y * BM;
    int block_col = blockIdx.x * BN;
    int tx = tid & 15, ty = tid >> 4;

    float acc[TM][TN];
    #pragma unroll
    for (int i = 0; i < TM; i++)
        #pragma unroll
        for (int j = 0; j < TN; j++) acc[i][j] = 0.f;

    for (int k0 = 0; k0 < K; k0 += BK) {
        // A tile: 128x16 -> 512 float4, 2 per thread (store transposed)
        #pragma unroll
        for (int i = 0; i < 2; i++) {
            int f = tid + i * 256;
            int row = f >> 2;
            int kc  = (f & 3) * 4;
            float4 v = *(const float4*)&A[(size_t)(block_row + row) * K + k0 + kc];
            As[kc + 0][row] = v.x;
            As[kc + 1][row] = v.y;
            As[kc + 2][row] = v.z;
            As[kc + 3][row] = v.w;
        }
        // B tile: 16x128 -> 512 float4, 2 per thread
        #pragma unroll
        for (int i = 0; i < 2; i++) {
            int f = tid + i * 256;
            int row = f >> 5;
            int col = (f & 31) * 4;
            *(float4*)&Bs[row][col] =
                *(const float4*)&B[(size_t)(k0 + row) * N + block_col + col];
        }
        __syncthreads();
        #pragma unroll
        for (int kk = 0; kk < BK; kk++) {
            float a[TM], bfr[TN];
            #pragma unroll
            for (int i = 0; i < TM; i++) a[i] = As[kk][ty * TM + i];
            #pragma unroll
            for (int j = 0; j < TN; j++) bfr[j] = Bs[kk][tx * TN + j];
            #pragma unroll
            for (int i = 0; i < TM; i++)
                #pragma unroll
                for (int j = 0; j < TN; j++)
                    acc[i][j] += a[i] * bfr[j];
        }
        __syncthreads();
    }
    #pragma unroll
    for (int i = 0; i < TM; i++) {
        int row = block_row + ty * TM + i;
        #pragma unroll
        for (int j = 0; j < TN; j++) {
            int col = block_col + tx * TN + j;
            float v = acc[i][j];
            if (bias) v += bias[col];
            if (res)  v += res[(size_t)row * N + col];
            C[(size_t)row * N + col] = v;
        }
    }
}

// ---------------- flash attention (causal, fp32) ----------------
// Q/K/V live in g_qkv rows [b*T+t][2304] at col offsets 0 / 768 / 1536 (+h*64)
#define FBM 64
#define FBN 32

__global__ __launch_bounds__(64)
void flash_attn_kernel(float* __restrict__ O) {
    __shared__ float Ks[FBN][HS];
    __shared__ float Vs[FBN][HS];
    __shared__ float Ss[FBM][FBN + 1];

    int qt = blockIdx.x;      // 0..31
    int h  = blockIdx.y;      // 0..11
    int b  = blockIdx.z;      // 0..1
    int r  = threadIdx.x;     // 0..63
    int qi = qt * FBM + r;

    const float* qrow = g_qkv + (size_t)(b * TT + qi) * (3 * DD) + h * HS;
    float q[HS], o[HS];
    #pragma unroll
    for (int d = 0; d < HS; d += 4) {
        float4 v = *(const float4*)&qrow[d];
        q[d] = v.x; q[d+1] = v.y; q[d+2] = v.z; q[d+3] = v.w;
    }
    #pragma unroll
    for (int d = 0; d < HS; d++) o[d] = 0.f;

    float m = -1e30f, l = 0.f;
    const float scale = rsqrtf((float)DD);   // NOTE: scale by embed_dim, not head_size
    int ntiles = 2 * qt + 2;

    for (int jt = 0; jt < ntiles; jt++) {
        int jb = jt * FBN;
        // cooperative K/V tile load: 32 rows x 64 cols, 64 threads -> half row each
        {
            int row = r >> 1;
            int c0  = (r & 1) * 32;
            const float* kp = g_qkv + (size_t)(b * TT + jb + row) * (3 * DD) + DD + h * HS + c0;
            const float* vp = kp + DD;
            #pragma unroll
            for (int c = 0; c < 32; c += 4) {
                *(float4*)&Ks[row][c0 + c] = *(const float4*)&kp[c];
                *(float4*)&Vs[row][c0 + c] = *(const float4*)&vp[c];
            }
        }
        __syncthreads();

        // scores for this thread's query row
        #pragma unroll 4
        for (int j = 0; j < FBN; j++) {
            float acc = 0.f;
            #pragma unroll
            for (int d = 0; d < HS; d += 4) {
                float4 kv = *(const float4*)&Ks[j][d];
                acc += q[d] * kv.x + q[d+1] * kv.y + q[d+2] * kv.z + q[d+3] * kv.w;
            }
            Ss[r][j] = (jb + j <= qi) ? acc * scale : -1e30f;
        }
        // online softmax update
        float tm = m;
        #pragma unroll
        for (int j = 0; j < FBN; j++) tm = fmaxf(tm, Ss[r][j]);
        float corr = __expf(m - tm);
        m = tm;
        l *= corr;
        #pragma unroll
        for (int d = 0; d < HS; d++) o[d] *= corr;
        for (int j = 0; j < FBN; j++) {
            float p = __expf(Ss[r][j] - m);
            l += p;
            #pragma unroll
            for (int d = 0; d < HS; d += 4) {
                float4 vv = *(const float4*)&Vs[j][d];
                o[d]   += p * vv.x;
                o[d+1] += p * vv.y;
                o[d+2] += p * vv.z;
                o[d+3] += p * vv.w;
            }
        }
        __syncthreads();
    }

    float inv = 1.0f / l;
    float* op = O + (size_t)(b * TT + qi) * DD + h * HS;
    #pragma unroll
    for (int d = 0; d < HS; d += 4) {
        float4 v;
        v.x = o[d] * inv; v.y = o[d+1] * inv; v.z = o[d+2] * inv; v.w = o[d+3] * inv;
        *(float4*)&op[d] = v;
    }
}

// ---------------- SwiGLU elementwise ----------------
__global__ void swiglu_kernel() {
    int idx = blockIdx.x * 256 + threadIdx.x;
    if (idx >= ROWS * HALF) return;
    int row = idx / HALF, col = idx % HALF;
    float a = g_u[(size_t)row * FF + col];
    float z = g_u[(size_t)row * FF + HALF + col];
    float sig = 1.0f / (1.0f + __expf(-z));
    g_gsw[idx] = z * sig * a;
}

// ---------------- launch ----------------
extern "C" void kernel_launch(void* const* d_in, const int* in_sizes, int n_in,
                              void* d_out, int out_size) {
    const float* x  = (const float*)d_in[0];
    const float* Wq = (const float*)d_in[1];
    const float* Wk = (const float*)d_in[2];
    const float* Wv = (const float*)d_in[3];
    const float* Wo = (const float*)d_in[4];
    const float* bo = (const float*)d_in[5];
    const float* W1 = (const float*)d_in[6];
    const float* b1 = (const float*)d_in[7];
    const float* W2 = (const float*)d_in[8];
    const float* b2 = (const float*)d_in[9];
    const float* g1 = (const float*)d_in[10];
    const float* g2 = (const float*)d_in[11];
    float* out = (float*)d_out;

    float *p_h, *p_wqkv, *p_qkv, *p_attn, *p_x1, *p_u, *p_gsw;
    cudaGetSymbolAddress((void**)&p_h,    g_h);
    cudaGetSymbolAddress((void**)&p_wqkv, g_wqkv);
    cudaGetSymbolAddress((void**)&p_qkv,  g_qkv);
    cudaGetSymbolAddress((void**)&p_attn, g_attn);
    cudaGetSymbolAddress((void**)&p_x1,   g_x1);
    cudaGetSymbolAddress((void**)&p_u,    g_u);
    cudaGetSymbolAddress((void**)&p_gsw,  g_gsw);

    // 1. pack QKV weights
    pack_wqkv_kernel<<<(DD * 3 * DD + 255) / 256, 256>>>(Wq, Wk, Wv);
    // 2. rmsnorm(x, g1) -> h
    rmsnorm_kernel<<<ROWS, 256>>>(x, g1, p_h);
    // 3. QKV = h @ Wqkv   [4096 x 2304]
    gemm_kernel<<<dim3((3 * DD) / BN, ROWS / BM), 256>>>(
        p_h, p_wqkv, p_qkv, nullptr, nullptr, ROWS, 3 * DD, DD);
    // 4. flash attention -> attn (heads concat)
    flash_attn_kernel<<<dim3(TT / FBM, HH, BB), FBM>>>(p_attn);
    // 5. x1 = x + attn @ Wo + bo
    gemm_kernel<<<dim3(DD / BN, ROWS / BM), 256>>>(
        p_attn, Wo, p_x1, bo, x, ROWS, DD, DD);
    // 6. rmsnorm(x1, g2) -> h (reuse)
    rmsnorm_kernel<<<ROWS, 256>>>(p_x1, g2, p_h);
    // 7. u = h @ W1 + b1   [4096 x 3072]
    gemm_kernel<<<dim3(FF / BN, ROWS / BM), 256>>>(
        p_h, W1, p_u, b1, nullptr, ROWS, FF, DD);
    // 8. swiglu: gsw = silu(gate) * a
    swiglu_kernel<<<(ROWS * HALF + 255) / 256, 256>>>();
    // 9. out = x1 + gsw @ W2 + b2
    gemm_kernel<<<dim3(DD / BN, ROWS / BM), 256>>>(
        p_gsw, W2, out, b2, p_x1, ROWS, DD, HALF);
}

// round 6
// speedup vs baseline: 2.0749x; 2.0749x over previous
#include <cuda_runtime.h>
#include <cuda_bf16.h>
#include <cstdint>
#include <cstdio>

// Problem constants
#define BB 2
#define TT 2048
#define DD 768
#define HH 12
#define HS 64
#define FF 3072
#define HALF 1536
#define ROWS (BB*TT)          // 4096

// ---------------- device scratch (no allocations allowed) ----------------
__device__ float g_h   [ROWS * DD];        // rmsnorm output (reused for h2)
__device__ float g_wqkv[DD * 3 * DD];      // packed QKV weight [768][2304]
__device__ float g_qkv [ROWS * 3 * DD];    // Q|K|V  [4096][2304]
__device__ float g_attn[ROWS * DD];        // attention output (heads concat)
__device__ float g_x1  [ROWS * DD];        // x + attn proj residual
__device__ float g_u   [ROWS * FF];        // FFN hidden
__device__ float g_gsw [ROWS * HALF];      // silu(gate)*a

// ---------------- helpers ----------------
__device__ __forceinline__ unsigned f2tf32(float f) {
    unsigned u;
    asm("cvt.rna.tf32.f32 %0, %1;" : "=r"(u) : "f"(f));
    return u;
}

__device__ __forceinline__ void mma_tf32(float c[4], const unsigned a[4], const unsigned b[2]) {
    asm volatile(
        "mma.sync.aligned.m16n8k8.row.col.f32.tf32.tf32.f32 "
        "{%0,%1,%2,%3}, {%4,%5,%6,%7}, {%8,%9}, {%0,%1,%2,%3};"
        : "+f"(c[0]), "+f"(c[1]), "+f"(c[2]), "+f"(c[3])
        : "r"(a[0]), "r"(a[1]), "r"(a[2]), "r"(a[3]), "r"(b[0]), "r"(b[1]));
}

// ---------------- pack Wq,Wk,Wv -> [d][which*768 + h*64 + k] ----------------
__global__ void pack_wqkv_kernel(const float* __restrict__ Wq,
                                 const float* __restrict__ Wk,
                                 const float* __restrict__ Wv) {
    int idx = blockIdx.x * 256 + threadIdx.x;
    if (idx >= DD * 3 * DD) return;
    int d   = idx / (3 * DD);
    int col = idx % (3 * DD);
    int which = col / DD;
    int rem   = col % DD;
    int h = rem / HS, k = rem % HS;
    const float* src = (which == 0) ? Wq : (which == 1) ? Wk : Wv;
    g_wqkv[idx] = src[(size_t)h * DD * HS + (size_t)d * HS + k];
}

// ---------------- RMSNorm: y = g * x / (rms + eps) ----------------
__global__ void rmsnorm_kernel(const float* __restrict__ X,
                               const float* __restrict__ g,
                               float* __restrict__ Y) {
    int row = blockIdx.x;
    const float* x = X + (size_t)row * DD;
    float* y = Y + (size_t)row * DD;
    __shared__ float red[256];
    int t = threadIdx.x;
    float ss = 0.f;
    #pragma unroll
    for (int i = t; i < DD; i += 256) { float v = x[i]; ss += v * v; }
    red[t] = ss; __syncthreads();
    #pragma unroll
    for (int s2 = 128; s2 > 0; s2 >>= 1) {
        if (t < s2) red[t] += red[t + s2];
        __syncthreads();
    }
    float rms = sqrtf(red[0] * (1.0f / DD));
    float inv = 1.0f / (rms + 1e-8f);
    #pragma unroll
    for (int i = t; i < DD; i += 256) y[i] = g[i] * x[i] * inv;
}

// ---------------- tf32 tensor-core GEMM: C = A[M,K] @ B[K,N] (+bias)(+res) ----
// BM=128, BN=128, BK=16.  8 warps, warp tile 32x64 (2x8 m16n8k8 fragments).
#define GBM 128
#define GBN 128
#define GBK 16
#define APITCH (GBK + 4)    // 20  (conflict-free a-frag LDS)
#define BPITCH (GBN + 8)    // 136 (conflict-free b-frag LDS)

__global__ __launch_bounds__(256)
void gemm_tf32_kernel(const float* __restrict__ A, const float* __restrict__ B,
                      float* __restrict__ C,
                      const float* __restrict__ bias, const float* __restrict__ res,
                      int M, int N, int K) {
    __shared__ unsigned As[GBM * APITCH];
    __shared__ unsigned Bs[GBK * BPITCH];

    int tid  = threadIdx.x;
    int warp = tid >> 5;
    int lane = tid & 31;
    int g  = lane >> 2;     // 0..7
    int t4 = lane & 3;      // 0..3
    int wm = (warp >> 1) * 32;   // 0,32,64,96
    int wn = (warp & 1) * 64;    // 0,64
    int block_row = blockIdx.y * GBM;
    int block_col = blockIdx.x * GBN;

    float c[2][8][4];
    #pragma unroll
    for (int mt = 0; mt < 2; mt++)
        #pragma unroll
        for (int nt = 0; nt < 8; nt++)
            #pragma unroll
            for (int q = 0; q < 4; q++) c[mt][nt][q] = 0.f;

    for (int k0 = 0; k0 < K; k0 += GBK) {
        // A tile 128x16: 512 float4, 2 per thread, natural layout [m][k]
        #pragma unroll
        for (int i = 0; i < 2; i++) {
            int f = tid + i * 256;
            int row = f >> 2;
            int kq  = (f & 3) * 4;
            float4 v = *(const float4*)&A[(size_t)(block_row + row) * K + k0 + kq];
            uint4 u;
            u.x = f2tf32(v.x); u.y = f2tf32(v.y); u.z = f2tf32(v.z); u.w = f2tf32(v.w);
            *(uint4*)&As[row * APITCH + kq] = u;
        }
        // B tile 16x128: natural layout [k][n]
        #pragma unroll
        for (int i = 0; i < 2; i++) {
            int f = tid + i * 256;
            int row = f >> 5;
            int col = (f & 31) * 4;
            float4 v = *(const float4*)&B[(size_t)(k0 + row) * N + block_col + col];
            uint4 u;
            u.x = f2tf32(v.x); u.y = f2tf32(v.y); u.z = f2tf32(v.z); u.w = f2tf32(v.w);
            *(uint4*)&Bs[row * BPITCH + col] = u;
        }
        __syncthreads();

        #pragma unroll
        for (int kk = 0; kk < GBK; kk += 8) {
            unsigned a[2][4];
            #pragma unroll
            for (int mt = 0; mt < 2; mt++) {
                int r0 = wm + mt * 16 + g;
                a[mt][0] = As[(r0    ) * APITCH + kk + t4];
                a[mt][1] = As[(r0 + 8) * APITCH + kk + t4];
                a[mt][2] = As[(r0    ) * APITCH + kk + t4 + 4];
                a[mt][3] = As[(r0 + 8) * APITCH + kk + t4 + 4];
            }
            unsigned b[8][2];
            #pragma unroll
            for (int nt = 0; nt < 8; nt++) {
                int cn = wn + nt * 8 + g;
                b[nt][0] = Bs[(kk + t4    ) * BPITCH + cn];
                b[nt][1] = Bs[(kk + t4 + 4) * BPITCH + cn];
            }
            #pragma unroll
            for (int mt = 0; mt < 2; mt++)
                #pragma unroll
                for (int nt = 0; nt < 8; nt++)
                    mma_tf32(c[mt][nt], a[mt], b[nt]);
        }
        __syncthreads();
    }

    // writeback: c0,c1 -> (row, col..col+1), c2,c3 -> (row+8, same cols)
    #pragma unroll
    for (int mt = 0; mt < 2; mt++) {
        int r0 = block_row + wm + mt * 16 + g;
        #pragma unroll
        for (int nt = 0; nt < 8; nt++) {
            int col = block_col + wn + nt * 8 + t4 * 2;
            float v0 = c[mt][nt][0], v1 = c[mt][nt][1];
            float v2 = c[mt][nt][2], v3 = c[mt][nt][3];
            if (bias) {
                float b0 = bias[col], b1 = bias[col + 1];
                v0 += b0; v1 += b1; v2 += b0; v3 += b1;
            }
            if (res) {
                v0 += res[(size_t)r0 * N + col];
                v1 += res[(size_t)r0 * N + col + 1];
                v2 += res[(size_t)(r0 + 8) * N + col];
                v3 += res[(size_t)(r0 + 8) * N + col + 1];
            }
            *(float2*)&C[(size_t)r0 * N + col]       = make_float2(v0, v1);
            *(float2*)&C[(size_t)(r0 + 8) * N + col] = make_float2(v2, v3);
        }
    }
}

// ---------------- flash attention (causal, fp32, tile-based) ----------------
// Q/K/V live in g_qkv rows [b*T+t][2304] at col offsets 0 / 768 / 1536 (+h*64)
// Block: 128 threads. 64-query x 64-key tiles. Thread (tx 0..15, ty 0..7)
// owns 8 query rows x 4 cols (keys in S phase, head-dims in PV phase).
#define ABM 64
#define ABN 64
#define FPITCH 68           // 64 + 4 pad
#define FSMEM_FLOATS (3 * ABM * FPITCH)   // Qs | K/P (aliased) | Vs

__global__ __launch_bounds__(128)
void flash_attn_kernel(float* __restrict__ O) {
    extern __shared__ float fsm[];
    float* Qs  = fsm;                       // [dim][query]  64x68
    float* KPs = fsm + ABM * FPITCH;        // K: [dim][key] then P: [key][query]
    float* Vs  = fsm + 2 * ABM * FPITCH;    // [key][dim]

    int qt = gridDim.x - 1 - blockIdx.x;    // longest blocks launch first
    int h  = blockIdx.y;
    int b  = blockIdx.z;
    int tid = threadIdx.x;
    int tx = tid & 15;      // 4 cols
    int ty = tid >> 4;      // 8 rows
    int q0 = qt * ABM;

    // load Q tile transposed: Qs[dim][query]
    {
        int row = tid >> 1;
        int c0  = (tid & 1) * 32;
        const float* qp = g_qkv + (size_t)(b * TT + q0 + row) * (3 * DD) + h * HS + c0;
        #pragma unroll
        for (int cc = 0; cc < 32; cc += 4) {
            float4 v = *(const float4*)&qp[cc];
            Qs[(c0 + cc + 0) * FPITCH + row] = v.x;
            Qs[(c0 + cc + 1) * FPITCH + row] = v.y;
            Qs[(c0 + cc + 2) * FPITCH + row] = v.z;
            Qs[(c0 + cc + 3) * FPITCH + row] = v.w;
        }
    }

    float o[8][4];
    float m[8], l[8];
    #pragma unroll
    for (int i = 0; i < 8; i++) {
        m[i] = -1e30f; l[i] = 0.f;
        #pragma unroll
        for (int d = 0; d < 4; d++) o[i][d] = 0.f;
    }
    const float scale = rsqrtf((float)DD);

    int ntiles = qt + 1;
    for (int jt = 0; jt < ntiles; jt++) {
        int j0 = jt * ABN;
        // load K (transposed) and V (natural)
        {
            int row = tid >> 1;
            int c0  = (tid & 1) * 32;
            const float* kp = g_qkv + (size_t)(b * TT + j0 + row) * (3 * DD) + DD + h * HS + c0;
            const float* vp = kp + DD;
            #pragma unroll
            for (int cc = 0; cc < 32; cc += 4) {
                float4 kv = *(const float4*)&kp[cc];
                KPs[(c0 + cc + 0) * FPITCH + row] = kv.x;
                KPs[(c0 + cc + 1) * FPITCH + row] = kv.y;
                KPs[(c0 + cc + 2) * FPITCH + row] = kv.z;
                KPs[(c0 + cc + 3) * FPITCH + row] = kv.w;
                *(float4*)&Vs[row * FPITCH + c0 + cc] = *(const float4*)&vp[cc];
            }
        }
        __syncthreads();

        // S = Q K^T  (8x4 register tile per thread)
        float s[8][4];
        #pragma unroll
        for (int i = 0; i < 8; i++)
            #pragma unroll
            for (int j = 0; j < 4; j++) s[i][j] = 0.f;

        #pragma unroll 8
        for (int kk = 0; kk < HS; kk++) {
            float4 a0 = *(const float4*)&Qs[kk * FPITCH + ty * 8];
            float4 a1 = *(const float4*)&Qs[kk * FPITCH + ty * 8 + 4];
            float4 bv = *(const float4*)&KPs[kk * FPITCH + tx * 4];
            float aa[8] = {a0.x, a0.y, a0.z, a0.w, a1.x, a1.y, a1.z, a1.w};
            float bb[4] = {bv.x, bv.y, bv.z, bv.w};
            #pragma unroll
            for (int i = 0; i < 8; i++)
                #pragma unroll
                for (int j = 0; j < 4; j++)
                    s[i][j] += aa[i] * bb[j];
        }
        __syncthreads();   // all warps done reading K; KPs may be reused for P

        // scale + causal mask (only diagonal tile needs masking)
        if (jt == ntiles - 1) {
            #pragma unroll
            for (int i = 0; i < 8; i++)
                #pragma unroll
                for (int j = 0; j < 4; j++)
                    s[i][j] = (j0 + tx * 4 + j <= q0 + ty * 8 + i) ? s[i][j] * scale : -1e30f;
        } else {
            #pragma unroll
            for (int i = 0; i < 8; i++)
                #pragma unroll
                for (int j = 0; j < 4; j++) s[i][j] *= scale;
        }

        // row max across 16 tx-lanes (lanes [0..15] / [16..31] are row groups)
        #pragma unroll
        for (int i = 0; i < 8; i++) {
            float pm = fmaxf(fmaxf(s[i][0], s[i][1]), fmaxf(s[i][2], s[i][3]));
            #pragma unroll
            for (int ofs = 1; ofs < 16; ofs <<= 1)
                pm = fmaxf(pm, __shfl_xor_sync(0xffffffffu, pm, ofs, 16));
            float mn = fmaxf(m[i], pm);
            float corr = __expf(m[i] - mn);
            m[i] = mn;
            float ps = 0.f;
            #pragma unroll
            for (int j = 0; j < 4; j++) {
                float p = __expf(s[i][j] - mn);
                s[i][j] = p;
                ps += p;
            }
            #pragma unroll
            for (int ofs = 1; ofs < 16; ofs <<= 1)
                ps += __shfl_xor_sync(0xffffffffu, ps, ofs, 16);
            l[i] = l[i] * corr + ps;
            #pragma unroll
            for (int d = 0; d < 4; d++) o[i][d] *= corr;
        }

        // write P transposed into KPs: P[key][query]
        #pragma unroll
        for (int j = 0; j < 4; j++) {
            *(float4*)&KPs[(tx * 4 + j) * FPITCH + ty * 8] =
                make_float4(s[0][j], s[1][j], s[2][j], s[3][j]);
            *(float4*)&KPs[(tx * 4 + j) * FPITCH + ty * 8 + 4] =
                make_float4(s[4][j], s[5][j], s[6][j], s[7][j]);
        }
        __syncthreads();

        // O += P V   (contract over keys)
        #pragma unroll 8
        for (int j = 0; j < ABN; j++) {
            float4 a0 = *(const float4*)&KPs[j * FPITCH + ty * 8];
            float4 a1 = *(const float4*)&KPs[j * FPITCH + ty * 8 + 4];
            float4 bv = *(const float4*)&Vs[j * FPITCH + tx * 4];
            float aa[8] = {a0.x, a0.y, a0.z, a0.w, a1.x, a1.y, a1.z, a1.w};
            float bb[4] = {bv.x, bv.y, bv.z, bv.w};
            #pragma unroll
            for (int i = 0; i < 8; i++)
                #pragma unroll
                for (int d = 0; d < 4; d++)
                    o[i][d] += aa[i] * bb[d];
        }
        __syncthreads();
    }

    // epilogue
    #pragma unroll
    for (int i = 0; i < 8; i++) {
        float inv = 1.0f / l[i];
        float4 v = make_float4(o[i][0] * inv, o[i][1] * inv, o[i][2] * inv, o[i][3] * inv);
        *(float4*)&O[(size_t)(b * TT + q0 + ty * 8 + i) * DD + h * HS + tx * 4] = v;
    }
}

// ---------------- SwiGLU elementwise ----------------
__global__ void swiglu_kernel() {
    int idx = blockIdx.x * 256 + threadIdx.x;
    if (idx >= ROWS * HALF) return;
    int row = idx / HALF, col = idx % HALF;
    float a = g_u[(size_t)row * FF + col];
    float z = g_u[(size_t)row * FF + HALF + col];
    float sig = 1.0f / (1.0f + __expf(-z));
    g_gsw[idx] = z * sig * a;
}

// ---------------- launch ----------------
extern "C" void kernel_launch(void* const* d_in, const int* in_sizes, int n_in,
                              void* d_out, int out_size) {
    const float* x  = (const float*)d_in[0];
    const float* Wq = (const float*)d_in[1];
    const float* Wk = (const float*)d_in[2];
    const float* Wv = (const float*)d_in[3];
    const float* Wo = (const float*)d_in[4];
    const float* bo = (const float*)d_in[5];
    const float* W1 = (const float*)d_in[6];
    const float* b1 = (const float*)d_in[7];
    const float* W2 = (const float*)d_in[8];
    const float* b2 = (const float*)d_in[9];
    const float* g1 = (const float*)d_in[10];
    const float* g2 = (const float*)d_in[11];
    float* out = (float*)d_out;

    float *p_h, *p_wqkv, *p_qkv, *p_attn, *p_x1, *p_u, *p_gsw;
    cudaGetSymbolAddress((void**)&p_h,    g_h);
    cudaGetSymbolAddress((void**)&p_wqkv, g_wqkv);
    cudaGetSymbolAddress((void**)&p_qkv,  g_qkv);
    cudaGetSymbolAddress((void**)&p_attn, g_attn);
    cudaGetSymbolAddress((void**)&p_x1,   g_x1);
    cudaGetSymbolAddress((void**)&p_u,    g_u);
    cudaGetSymbolAddress((void**)&p_gsw,  g_gsw);

    const int fa_smem = FSMEM_FLOATS * (int)sizeof(float);   // 52224 bytes
    cudaFuncSetAttribute(flash_attn_kernel,
                         cudaFuncAttributeMaxDynamicSharedMemorySize, fa_smem);

    // 1. pack QKV weights
    pack_wqkv_kernel<<<(DD * 3 * DD + 255) / 256, 256>>>(Wq, Wk, Wv);
    // 2. rmsnorm(x, g1) -> h
    rmsnorm_kernel<<<ROWS, 256>>>(x, g1, p_h);
    // 3. QKV = h @ Wqkv   [4096 x 2304]
    gemm_tf32_kernel<<<dim3((3 * DD) / GBN, ROWS / GBM), 256>>>(
        p_h, p_wqkv, p_qkv, nullptr, nullptr, ROWS, 3 * DD, DD);
    // 4. flash attention -> attn (heads concat)
    flash_attn_kernel<<<dim3(TT / ABM, HH, BB), 128, fa_smem>>>(p_attn);
    // 5. x1 = x + attn @ Wo + bo
    gemm_tf32_kernel<<<dim3(DD / GBN, ROWS / GBM), 256>>>(
        p_attn, Wo, p_x1, bo, x, ROWS, DD, DD);
    // 6. rmsnorm(x1, g2) -> h (reuse)
    rmsnorm_kernel<<<ROWS, 256>>>(p_x1, g2, p_h);
    // 7. u = h @ W1 + b1   [4096 x 3072]
    gemm_tf32_kernel<<<dim3(FF / GBN, ROWS / GBM), 256>>>(
        p_h, W1, p_u, b1, nullptr, ROWS, FF, DD);
    // 8. swiglu: gsw = silu(gate) * a
    swiglu_kernel<<<(ROWS * HALF + 255) / 256, 256>>>();
    // 9. out = x1 + gsw @ W2 + b2
    gemm_tf32_kernel<<<dim3(DD / GBN, ROWS / GBM), 256>>>(
        p_gsw, W2, out, b2, p_x1, ROWS, DD, HALF);
}

// round 8
// speedup vs baseline: 2.7292x; 1.3154x over previous
#include <cuda_runtime.h>
#include <cuda_bf16.h>
#include <cstdint>
#include <cstdio>

// Problem constants
#define BB 2
#define TT 2048
#define DD 768
#define HH 12
#define HS 64
#define FF 3072
#define HALF 1536
#define ROWS (BB*TT)          // 4096

// ---------------- device scratch (no allocations allowed) ----------------
__device__ float g_h   [ROWS * DD];        // rmsnorm output (reused for h2)
__device__ float g_wqkv[DD * 3 * DD];      // packed QKV weight [768][2304]
__device__ float g_qkv [ROWS * 3 * DD];    // Q|K|V  [4096][2304]
__device__ float g_attn[ROWS * DD];        // attention output (heads concat)
__device__ float g_x1  [ROWS * DD];        // x + attn proj residual
__device__ float g_u   [ROWS * FF];        // FFN hidden
__device__ float g_gsw [ROWS * HALF];      // silu(gate)*a

// ---------------- helpers ----------------
__device__ __forceinline__ unsigned f2tf32(float f) {
    unsigned u;
    asm("cvt.rna.tf32.f32 %0, %1;" : "=r"(u) : "f"(f));
    return u;
}

__device__ __forceinline__ void mma_tf32(float c[4], const unsigned a[4], const unsigned b[2]) {
    asm volatile(
        "mma.sync.aligned.m16n8k8.row.col.f32.tf32.tf32.f32 "
        "{%0,%1,%2,%3}, {%4,%5,%6,%7}, {%8,%9}, {%0,%1,%2,%3};"
        : "+f"(c[0]), "+f"(c[1]), "+f"(c[2]), "+f"(c[3])
        : "r"(a[0]), "r"(a[1]), "r"(a[2]), "r"(a[3]), "r"(b[0]), "r"(b[1]));
}

// ---------------- pack Wq,Wk,Wv -> [d][which*768 + h*64 + k] ----------------
__global__ void pack_wqkv_kernel(const float* __restrict__ Wq,
                                 const float* __restrict__ Wk,
                                 const float* __restrict__ Wv) {
    int idx = blockIdx.x * 256 + threadIdx.x;
    if (idx >= DD * 3 * DD) return;
    int d   = idx / (3 * DD);
    int col = idx % (3 * DD);
    int which = col / DD;
    int rem   = col % DD;
    int h = rem / HS, k = rem % HS;
    const float* src = (which == 0) ? Wq : (which == 1) ? Wk : Wv;
    g_wqkv[idx] = src[(size_t)h * DD * HS + (size_t)d * HS + k];
}

// ---------------- RMSNorm: y = g * x / (rms + eps) ----------------
__global__ void rmsnorm_kernel(const float* __restrict__ X,
                               const float* __restrict__ g,
                               float* __restrict__ Y) {
    int row = blockIdx.x;
    const float* x = X + (size_t)row * DD;
    float* y = Y + (size_t)row * DD;
    __shared__ float red[256];
    int t = threadIdx.x;
    float ss = 0.f;
    #pragma unroll
    for (int i = t; i < DD; i += 256) { float v = x[i]; ss += v * v; }
    red[t] = ss; __syncthreads();
    #pragma unroll
    for (int s2 = 128; s2 > 0; s2 >>= 1) {
        if (t < s2) red[t] += red[t + s2];
        __syncthreads();
    }
    float rms = sqrtf(red[0] * (1.0f / DD));
    float inv = 1.0f / (rms + 1e-8f);
    #pragma unroll
    for (int i = t; i < DD; i += 256) y[i] = g[i] * x[i] * inv;
}

// ---------------- tf32 tensor-core GEMM: C = A[M,K] @ B[K,N] (+bias)(+res) ----
#define GBM 128
#define GBN 128
#define GBK 16
#define APITCH (GBK + 4)    // 20
#define BPITCH (GBN + 8)    // 136

__global__ __launch_bounds__(256)
void gemm_tf32_kernel(const float* __restrict__ A, const float* __restrict__ B,
                      float* __restrict__ C,
                      const float* __restrict__ bias, const float* __restrict__ res,
                      int M, int N, int K) {
    __shared__ unsigned As[GBM * APITCH];
    __shared__ unsigned Bs[GBK * BPITCH];

    int tid  = threadIdx.x;
    int warp = tid >> 5;
    int lane = tid & 31;
    int g  = lane >> 2;
    int t4 = lane & 3;
    int wm = (warp >> 1) * 32;
    int wn = (warp & 1) * 64;
    int block_row = blockIdx.y * GBM;
    int block_col = blockIdx.x * GBN;

    float c[2][8][4];
    #pragma unroll
    for (int mt = 0; mt < 2; mt++)
        #pragma unroll
        for (int nt = 0; nt < 8; nt++)
            #pragma unroll
            for (int q = 0; q < 4; q++) c[mt][nt][q] = 0.f;

    for (int k0 = 0; k0 < K; k0 += GBK) {
        #pragma unroll
        for (int i = 0; i < 2; i++) {
            int f = tid + i * 256;
            int row = f >> 2;
            int kq  = (f & 3) * 4;
            float4 v = *(const float4*)&A[(size_t)(block_row + row) * K + k0 + kq];
            uint4 u;
            u.x = f2tf32(v.x); u.y = f2tf32(v.y); u.z = f2tf32(v.z); u.w = f2tf32(v.w);
            *(uint4*)&As[row * APITCH + kq] = u;
        }
        #pragma unroll
        for (int i = 0; i < 2; i++) {
            int f = tid + i * 256;
            int row = f >> 5;
            int col = (f & 31) * 4;
            float4 v = *(const float4*)&B[(size_t)(k0 + row) * N + block_col + col];
            uint4 u;
            u.x = f2tf32(v.x); u.y = f2tf32(v.y); u.z = f2tf32(v.z); u.w = f2tf32(v.w);
            *(uint4*)&Bs[row * BPITCH + col] = u;
        }
        __syncthreads();

        #pragma unroll
        for (int kk = 0; kk < GBK; kk += 8) {
            unsigned a[2][4];
            #pragma unroll
            for (int mt = 0; mt < 2; mt++) {
                int r0 = wm + mt * 16 + g;
                a[mt][0] = As[(r0    ) * APITCH + kk + t4];
                a[mt][1] = As[(r0 + 8) * APITCH + kk + t4];
                a[mt][2] = As[(r0    ) * APITCH + kk + t4 + 4];
                a[mt][3] = As[(r0 + 8) * APITCH + kk + t4 + 4];
            }
            unsigned b[8][2];
            #pragma unroll
            for (int nt = 0; nt < 8; nt++) {
                int cn = wn + nt * 8 + g;
                b[nt][0] = Bs[(kk + t4    ) * BPITCH + cn];
                b[nt][1] = Bs[(kk + t4 + 4) * BPITCH + cn];
            }
            #pragma unroll
            for (int mt = 0; mt < 2; mt++)
                #pragma unroll
                for (int nt = 0; nt < 8; nt++)
                    mma_tf32(c[mt][nt], a[mt], b[nt]);
        }
        __syncthreads();
    }

    #pragma unroll
    for (int mt = 0; mt < 2; mt++) {
        int r0 = block_row + wm + mt * 16 + g;
        #pragma unroll
        for (int nt = 0; nt < 8; nt++) {
            int col = block_col + wn + nt * 8 + t4 * 2;
            float v0 = c[mt][nt][0], v1 = c[mt][nt][1];
            float v2 = c[mt][nt][2], v3 = c[mt][nt][3];
            if (bias) {
                float b0 = bias[col], b1 = bias[col + 1];
                v0 += b0; v1 += b1; v2 += b0; v3 += b1;
            }
            if (res) {
                v0 += res[(size_t)r0 * N + col];
                v1 += res[(size_t)r0 * N + col + 1];
                v2 += res[(size_t)(r0 + 8) * N + col];
                v3 += res[(size_t)(r0 + 8) * N + col + 1];
            }
            *(float2*)&C[(size_t)r0 * N + col]       = make_float2(v0, v1);
            *(float2*)&C[(size_t)(r0 + 8) * N + col] = make_float2(v2, v3);
        }
    }
}

// ---------------- flash attention (causal, tf32 tensor cores) ----------------
// Q/K/V live in g_qkv rows [b*T+t][2304] at col offsets 0 / 768 / 1536 (+h*64)
// 64-query x 64-key tiles, 128 threads (4 warps), warp w owns rows [16w,16w+16).
// S = Q K^T and O += P V both via m16n8k8 tf32 MMA.
#define AQ 64
#define AK 64
#define KPITCH 72           // B-frag loads conflict-free: (8*t4 + g) distinct mod 32
#define PPITCH 68           // A-frag loads conflict-free: (4*g + t4) distinct mod 32
#define FA_SMEM ((2 * HS * KPITCH + AQ * PPITCH) * 4)   // 54272 bytes

__global__ __launch_bounds__(128)
void flash_attn_tc_kernel(float* __restrict__ O) {
    extern __shared__ unsigned fsm[];
    unsigned* Ks = fsm;                       // K^T: [dim][key]  64x72
    unsigned* Vs = fsm + HS * KPITCH;         // V:   [key][dim]  64x72
    unsigned* Ps = fsm + 2 * HS * KPITCH;     // Q staging, then P: [row][col] 64x68

    int qt = gridDim.x - 1 - blockIdx.x;      // longest blocks first
    int h  = blockIdx.y;
    int b  = blockIdx.z;
    int tid = threadIdx.x;
    int warp = tid >> 5, lane = tid & 31;
    int g = lane >> 2, t4 = lane & 3;
    int q0 = qt * AQ;
    int wrow = warp * 16;

    // ---- stage Q tile into Ps (tf32 bits), coalesced ----
    {
        int row = tid >> 1;
        int c0  = (tid & 1) * 32;
        const float* qp = g_qkv + (size_t)(b * TT + q0 + row) * (3 * DD) + h * HS + c0;
        #pragma unroll
        for (int cc = 0; cc < 32; cc += 4) {
            float4 v = *(const float4*)&qp[cc];
            uint4 u;
            u.x = f2tf32(v.x); u.y = f2tf32(v.y); u.z = f2tf32(v.z); u.w = f2tf32(v.w);
            Ps[row * PPITCH + c0 + cc + 0] = u.x;
            Ps[row * PPITCH + c0 + cc + 1] = u.y;
            Ps[row * PPITCH + c0 + cc + 2] = u.z;
            Ps[row * PPITCH + c0 + cc + 3] = u.w;
        }
    }
    __syncthreads();

    // ---- extract persistent Q A-fragments (16 rows per warp, 8 k-steps) ----
    unsigned qa[8][4];
    #pragma unroll
    for (int kk = 0; kk < 8; kk++) {
        qa[kk][0] = Ps[(wrow + g    ) * PPITCH + kk * 8 + t4];
        qa[kk][1] = Ps[(wrow + g + 8) * PPITCH + kk * 8 + t4];
        qa[kk][2] = Ps[(wrow + g    ) * PPITCH + kk * 8 + t4 + 4];
        qa[kk][3] = Ps[(wrow + g + 8) * PPITCH + kk * 8 + t4 + 4];
    }
    __syncthreads();   // everyone done reading Q before Ps is reused for P

    float oc[8][4];
    #pragma unroll
    for (int nt = 0; nt < 8; nt++)
        #pragma unroll
        for (int q = 0; q < 4; q++) oc[nt][q] = 0.f;
    float m0 = -1e30f, m1 = -1e30f, l0 = 0.f, l1 = 0.f;
    const float scale = rsqrtf((float)DD);

    int ntiles = qt + 1;
    for (int jt = 0; jt < ntiles; jt++) {
        __syncthreads();   // previous tile's MMA reads of Ks/Vs complete
        // ---- load K (transposed, tf32) and V (natural, tf32) ----
        {
            int row = tid >> 1;
            int c0  = (tid & 1) * 32;
            const float* kp = g_qkv + (size_t)(b * TT + jt * AK + row) * (3 * DD) + DD + h * HS + c0;
            const float* vp = kp + DD;
            #pragma unroll
            for (int cc = 0; cc < 32; cc += 4) {
                float4 kv = *(const float4*)&kp[cc];
                Ks[(c0 + cc + 0) * KPITCH + row] = f2tf32(kv.x);
                Ks[(c0 + cc + 1) * KPITCH + row] = f2tf32(kv.y);
                Ks[(c0 + cc + 2) * KPITCH + row] = f2tf32(kv.z);
                Ks[(c0 + cc + 3) * KPITCH + row] = f2tf32(kv.w);
                float4 vv = *(const float4*)&vp[cc];
                uint4 u;
                u.x = f2tf32(vv.x); u.y = f2tf32(vv.y); u.z = f2tf32(vv.z); u.w = f2tf32(vv.w);
                *(uint4*)&Vs[row * KPITCH + c0 + cc] = u;
            }
        }
        __syncthreads();

        // ---- S = Q K^T ----
        float sc[8][4];
        #pragma unroll
        for (int nt = 0; nt < 8; nt++)
            #pragma unroll
            for (int q = 0; q < 4; q++) sc[nt][q] = 0.f;
        #pragma unroll
        for (int kk = 0; kk < 8; kk++) {
            #pragma unroll
            for (int nt = 0; nt < 8; nt++) {
                unsigned bf[2];
                bf[0] = Ks[(kk * 8 + t4    ) * KPITCH + nt * 8 + g];
                bf[1] = Ks[(kk * 8 + t4 + 4) * KPITCH + nt * 8 + g];
                mma_tf32(sc[nt], qa[kk], bf);
            }
        }

        // ---- scale + causal mask (diagonal tile only) ----
        if (jt == ntiles - 1) {
            int r0 = wrow + g, r1 = wrow + g + 8;
            #pragma unroll
            for (int nt = 0; nt < 8; nt++) {
                int c0i = nt * 8 + 2 * t4, c1i = c0i + 1;
                sc[nt][0] = (c0i <= r0) ? sc[nt][0] * scale : -1e30f;
                sc[nt][1] = (c1i <= r0) ? sc[nt][1] * scale : -1e30f;
                sc[nt][2] = (c0i <= r1) ? sc[nt][2] * scale : -1e30f;
                sc[nt][3] = (c1i <= r1) ? sc[nt][3] * scale : -1e30f;
            }
        } else {
            #pragma unroll
            for (int nt = 0; nt < 8; nt++)
                #pragma unroll
                for (int q = 0; q < 4; q++) sc[nt][q] *= scale;
        }

        // ---- online softmax (rows g and g+8; reduce over 4 lanes sharing g) ----
        float pm0 = -1e30f, pm1 = -1e30f;
        #pragma unroll
        for (int nt = 0; nt < 8; nt++) {
            pm0 = fmaxf(pm0, fmaxf(sc[nt][0], sc[nt][1]));
            pm1 = fmaxf(pm1, fmaxf(sc[nt][2], sc[nt][3]));
        }
        #pragma unroll
        for (int ofs = 1; ofs < 4; ofs <<= 1) {
            pm0 = fmaxf(pm0, __shfl_xor_sync(0xffffffffu, pm0, ofs, 4));
            pm1 = fmaxf(pm1, __shfl_xor_sync(0xffffffffu, pm1, ofs, 4));
        }
        float mn0 = fmaxf(m0, pm0), mn1 = fmaxf(m1, pm1);
        float corr0 = __expf(m0 - mn0), corr1 = __expf(m1 - mn1);
        m0 = mn0; m1 = mn1;
        l0 *= corr0; l1 *= corr1;
        #pragma unroll
        for (int nt = 0; nt < 8; nt++) {
            oc[nt][0] *= corr0; oc[nt][1] *= corr0;
            oc[nt][2] *= corr1; oc[nt][3] *= corr1;
        }
        // exponentiate + write P (tf32) to warp-private rows of Ps
        #pragma unroll
        for (int nt = 0; nt < 8; nt++) {
            float p0 = __expf(sc[nt][0] - m0);
            float p1 = __expf(sc[nt][1] - m0);
            float p2 = __expf(sc[nt][2] - m1);
            float p3 = __expf(sc[nt][3] - m1);
            l0 += p0 + p1; l1 += p2 + p3;
            int cc = nt * 8 + 2 * t4;
            Ps[(wrow + g    ) * PPITCH + cc    ] = f2tf32(p0);
            Ps[(wrow + g    ) * PPITCH + cc + 1] = f2tf32(p1);
            Ps[(wrow + g + 8) * PPITCH + cc    ] = f2tf32(p2);
            Ps[(wrow + g + 8) * PPITCH + cc + 1] = f2tf32(p3);
        }
        __syncwarp();

        // ---- O += P V ----
        #pragma unroll
        for (int kk = 0; kk < 8; kk++) {
            unsigned pa[4];
            pa[0] = Ps[(wrow + g    ) * PPITCH + kk * 8 + t4];
            pa[1] = Ps[(wrow + g + 8) * PPITCH + kk * 8 + t4];
            pa[2] = Ps[(wrow + g    ) * PPITCH + kk * 8 + t4 + 4];
            pa[3] = Ps[(wrow + g + 8) * PPITCH + kk * 8 + t4 + 4];
            #pragma unroll
            for (int nt = 0; nt < 8; nt++) {
                unsigned bf[2];
                bf[0] = Vs[(kk * 8 + t4    ) * KPITCH + nt * 8 + g];
                bf[1] = Vs[(kk * 8 + t4 + 4) * KPITCH + nt * 8 + g];
                mma_tf32(oc[nt], pa, bf);
            }
        }
        __syncwarp();   // P reads done before next tile's stores
    }

    // ---- epilogue: reduce l over the 4 lanes, normalize, write ----
    #pragma unroll
    for (int ofs = 1; ofs < 4; ofs <<= 1) {
        l0 += __shfl_xor_sync(0xffffffffu, l0, ofs, 4);
        l1 += __shfl_xor_sync(0xffffffffu, l1, ofs, 4);
    }
    float inv0 = 1.0f / l0, inv1 = 1.0f / l1;
    #pragma unroll
    for (int nt = 0; nt < 8; nt++) {
        int col = h * HS + nt * 8 + 2 * t4;
        size_t r0 = (size_t)(b * TT + q0 + wrow + g) * DD;
        size_t r1 = (size_t)(b * TT + q0 + wrow + g + 8) * DD;
        *(float2*)&O[r0 + col] = make_float2(oc[nt][0] * inv0, oc[nt][1] * inv0);
        *(float2*)&O[r1 + col] = make_float2(oc[nt][2] * inv1, oc[nt][3] * inv1);
    }
}

// ---------------- SwiGLU elementwise ----------------
__global__ void swiglu_kernel() {
    int idx = blockIdx.x * 256 + threadIdx.x;
    if (idx >= ROWS * HALF) return;
    int row = idx / HALF, col = idx % HALF;
    float a = g_u[(size_t)row * FF + col];
    float z = g_u[(size_t)row * FF + HALF + col];
    float sig = 1.0f / (1.0f + __expf(-z));
    g_gsw[idx] = z * sig * a;
}

// ---------------- launch ----------------
extern "C" void kernel_launch(void* const* d_in, const int* in_sizes, int n_in,
                              void* d_out, int out_size) {
    const float* x  = (const float*)d_in[0];
    const float* Wq = (const float*)d_in[1];
    const float* Wk = (const float*)d_in[2];
    const float* Wv = (const float*)d_in[3];
    const float* Wo = (const float*)d_in[4];
    const float* bo = (const float*)d_in[5];
    const float* W1 = (const float*)d_in[6];
    const float* b1 = (const float*)d_in[7];
    const float* W2 = (const float*)d_in[8];
    const float* b2 = (const float*)d_in[9];
    const float* g1 = (const float*)d_in[10];
    const float* g2 = (const float*)d_in[11];
    float* out = (float*)d_out;

    float *p_h, *p_wqkv, *p_qkv, *p_attn, *p_x1, *p_u, *p_gsw;
    cudaGetSymbolAddress((void**)&p_h,    g_h);
    cudaGetSymbolAddress((void**)&p_wqkv, g_wqkv);
    cudaGetSymbolAddress((void**)&p_qkv,  g_qkv);
    cudaGetSymbolAddress((void**)&p_attn, g_attn);
    cudaGetSymbolAddress((void**)&p_x1,   g_x1);
    cudaGetSymbolAddress((void**)&p_u,    g_u);
    cudaGetSymbolAddress((void**)&p_gsw,  g_gsw);

    cudaFuncSetAttribute(flash_attn_tc_kernel,
                         cudaFuncAttributeMaxDynamicSharedMemorySize, FA_SMEM);

    // 1. pack QKV weights
    pack_wqkv_kernel<<<(DD * 3 * DD + 255) / 256, 256>>>(Wq, Wk, Wv);
    // 2. rmsnorm(x, g1) -> h
    rmsnorm_kernel<<<ROWS, 256>>>(x, g1, p_h);
    // 3. QKV = h @ Wqkv   [4096 x 2304]
    gemm_tf32_kernel<<<dim3((3 * DD) / GBN, ROWS / GBM), 256>>>(
        p_h, p_wqkv, p_qkv, nullptr, nullptr, ROWS, 3 * DD, DD);
    // 4. flash attention (tensor cores) -> attn
    flash_attn_tc_kernel<<<dim3(TT / AQ, HH, BB), 128, FA_SMEM>>>(p_attn);
    // 5. x1 = x + attn @ Wo + bo
    gemm_tf32_kernel<<<dim3(DD / GBN, ROWS / GBM), 256>>>(
        p_attn, Wo, p_x1, bo, x, ROWS, DD, DD);
    // 6. rmsnorm(x1, g2) -> h (reuse)
    rmsnorm_kernel<<<ROWS, 256>>>(p_x1, g2, p_h);
    // 7. u = h @ W1 + b1   [4096 x 3072]
    gemm_tf32_kernel<<<dim3(FF / GBN, ROWS / GBM), 256>>>(
        p_h, W1, p_u, b1, nullptr, ROWS, FF, DD);
    // 8. swiglu: gsw = silu(gate) * a
    swiglu_kernel<<<(ROWS * HALF + 255) / 256, 256>>>();
    // 9. out = x1 + gsw @ W2 + b2
    gemm_tf32_kernel<<<dim3(DD / GBN, ROWS / GBM), 256>>>(
        p_gsw, W2, out, b2, p_x1, ROWS, DD, HALF);
}

// round 10
// speedup vs baseline: 3.9682x; 1.4540x over previous
#include <cuda_runtime.h>
#include <cuda_fp16.h>
#include <cuda_bf16.h>
#include <cstdint>
#include <cstdio>

// Problem constants
#define BB 2
#define TT 2048
#define DD 768
#define HH 12
#define HS 64
#define FF 3072
#define HALF 1536
#define ROWS (BB*TT)          // 4096

// ---------------- device scratch (no allocations allowed) ----------------
__device__ float g_h   [ROWS * DD];        // rmsnorm output (reused for h2)
__device__ float g_wqkv[DD * 3 * DD];      // packed QKV weight [768][2304]
__device__ float g_qkv [ROWS * 3 * DD];    // Q|K|V  [4096][2304]
__device__ float g_attn[ROWS * DD];        // attention output (heads concat)
__device__ float g_x1  [ROWS * DD];        // x + attn proj residual
__device__ float g_u   [ROWS * FF];        // FFN hidden
__device__ float g_gsw [ROWS * HALF];      // silu(gate)*a

// ---------------- helpers ----------------
__device__ __forceinline__ unsigned packh2(float lo, float hi) {
    __half2 h = __floats2half2_rn(lo, hi);
    return *reinterpret_cast<unsigned*>(&h);
}

// m16n8k16 fp16 MMA, fp32 accumulate
__device__ __forceinline__ void mma_fp16(float c[4], const unsigned a[4], const unsigned b[2]) {
    asm volatile(
        "mma.sync.aligned.m16n8k16.row.col.f32.f16.f16.f32 "
        "{%0,%1,%2,%3}, {%4,%5,%6,%7}, {%8,%9}, {%0,%1,%2,%3};"
        : "+f"(c[0]), "+f"(c[1]), "+f"(c[2]), "+f"(c[3])
        : "r"(a[0]), "r"(a[1]), "r"(a[2]), "r"(a[3]), "r"(b[0]), "r"(b[1]));
}

// ---------------- pack Wq,Wk,Wv -> [d][which*768 + h*64 + k] ----------------
__global__ void pack_wqkv_kernel(const float* __restrict__ Wq,
                                 const float* __restrict__ Wk,
                                 const float* __restrict__ Wv) {
    int idx = blockIdx.x * 256 + threadIdx.x;
    if (idx >= DD * 3 * DD) return;
    int d   = idx / (3 * DD);
    int col = idx % (3 * DD);
    int which = col / DD;
    int rem   = col % DD;
    int h = rem / HS, k = rem % HS;
    const float* src = (which == 0) ? Wq : (which == 1) ? Wk : Wv;
    g_wqkv[idx] = src[(size_t)h * DD * HS + (size_t)d * HS + k];
}

// ---------------- RMSNorm: y = g * x / (rms + eps) ----------------
__global__ void rmsnorm_kernel(const float* __restrict__ X,
                               const float* __restrict__ g,
                               float* __restrict__ Y) {
    int row = blockIdx.x;
    const float* x = X + (size_t)row * DD;
    float* y = Y + (size_t)row * DD;
    __shared__ float red[256];
    int t = threadIdx.x;
    float ss = 0.f;
    #pragma unroll
    for (int i = t; i < DD; i += 256) { float v = x[i]; ss += v * v; }
    red[t] = ss; __syncthreads();
    #pragma unroll
    for (int s2 = 128; s2 > 0; s2 >>= 1) {
        if (t < s2) red[t] += red[t + s2];
        __syncthreads();
    }
    float rms = sqrtf(red[0] * (1.0f / DD));
    float inv = 1.0f / (rms + 1e-8f);
    #pragma unroll
    for (int i = t; i < DD; i += 256) y[i] = g[i] * x[i] * inv;
}

// ---------------- fp16 tensor-core GEMM: C = A[M,K] @ B[K,N] (+bias)(+res) ----
// BM=128, BN=128, BK=16. 8 warps, warp tile 32x64 (2x8 m16n8k16 fragments).
// Asu[m][kp]: u32 packs halves (2kp, 2kp+1) along k. pitch 12 u32.
// Bsu[kp][n]: u32 packs halves of rows 2kp,2kp+1 at col n. pitch 136 u32.
#define GBM 128
#define GBN 128
#define GBK 16
#define APITCH 12           // 8 k-pairs + 4 pad
#define BPITCH (GBN + 8)    // 136

__global__ __launch_bounds__(256)
void gemm_fp16_kernel(const float* __restrict__ A, const float* __restrict__ B,
                      float* __restrict__ C,
                      const float* __restrict__ bias, const float* __restrict__ res,
                      int M, int N, int K) {
    __shared__ unsigned Asu[GBM * APITCH];
    __shared__ unsigned Bsu[(GBK / 2) * BPITCH];

    int tid  = threadIdx.x;
    int warp = tid >> 5;
    int lane = tid & 31;
    int g  = lane >> 2;
    int t4 = lane & 3;
    int wm = (warp >> 1) * 32;
    int wn = (warp & 1) * 64;
    int block_row = blockIdx.y * GBM;
    int block_col = blockIdx.x * GBN;

    float c[2][8][4];
    #pragma unroll
    for (int mt = 0; mt < 2; mt++)
        #pragma unroll
        for (int nt = 0; nt < 8; nt++)
            #pragma unroll
            for (int q = 0; q < 4; q++) c[mt][nt][q] = 0.f;

    for (int k0 = 0; k0 < K; k0 += GBK) {
        // A tile 128x16 floats -> packed pairs. 512 float4-tasks, 2 per thread.
        #pragma unroll
        for (int i = 0; i < 2; i++) {
            int f = tid + i * 256;
            int row = f >> 2;
            int kq  = (f & 3) * 4;       // float col
            float4 v = *(const float4*)&A[(size_t)(block_row + row) * K + k0 + kq];
            Asu[row * APITCH + (kq >> 1)    ] = packh2(v.x, v.y);
            Asu[row * APITCH + (kq >> 1) + 1] = packh2(v.z, v.w);
        }
        // B tile: 8 k-pairs x 128 cols -> 256 float4-tasks, 1 per thread. (FIX)
        {
            int r   = tid >> 5;          // k-pair 0..7
            int col = (tid & 31) * 4;
            const float* b0p = &B[(size_t)(k0 + 2 * r) * N + block_col + col];
            float4 va = *(const float4*)b0p;
            float4 vb = *(const float4*)(b0p + N);
            Bsu[r * BPITCH + col    ] = packh2(va.x, vb.x);
            Bsu[r * BPITCH + col + 1] = packh2(va.y, vb.y);
            Bsu[r * BPITCH + col + 2] = packh2(va.z, vb.z);
            Bsu[r * BPITCH + col + 3] = packh2(va.w, vb.w);
        }
        __syncthreads();

        unsigned a[2][4];
        #pragma unroll
        for (int mt = 0; mt < 2; mt++) {
            int r0 = wm + mt * 16 + g;
            a[mt][0] = Asu[(r0    ) * APITCH + t4];
            a[mt][1] = Asu[(r0 + 8) * APITCH + t4];
            a[mt][2] = Asu[(r0    ) * APITCH + t4 + 4];
            a[mt][3] = Asu[(r0 + 8) * APITCH + t4 + 4];
        }
        unsigned b[8][2];
        #pragma unroll
        for (int nt = 0; nt < 8; nt++) {
            int cn = wn + nt * 8 + g;
            b[nt][0] = Bsu[(t4    ) * BPITCH + cn];
            b[nt][1] = Bsu[(t4 + 4) * BPITCH + cn];
        }
        #pragma unroll
        for (int mt = 0; mt < 2; mt++)
            #pragma unroll
            for (int nt = 0; nt < 8; nt++)
                mma_fp16(c[mt][nt], a[mt], b[nt]);
        __syncthreads();
    }

    #pragma unroll
    for (int mt = 0; mt < 2; mt++) {
        int r0 = block_row + wm + mt * 16 + g;
        #pragma unroll
        for (int nt = 0; nt < 8; nt++) {
            int col = block_col + wn + nt * 8 + t4 * 2;
            float v0 = c[mt][nt][0], v1 = c[mt][nt][1];
            float v2 = c[mt][nt][2], v3 = c[mt][nt][3];
            if (bias) {
                float b0 = bias[col], b1 = bias[col + 1];
                v0 += b0; v1 += b1; v2 += b0; v3 += b1;
            }
            if (res) {
                v0 += res[(size_t)r0 * N + col];
                v1 += res[(size_t)r0 * N + col + 1];
                v2 += res[(size_t)(r0 + 8) * N + col];
                v3 += res[(size_t)(r0 + 8) * N + col + 1];
            }
            *(float2*)&C[(size_t)r0 * N + col]       = make_float2(v0, v1);
            *(float2*)&C[(size_t)(r0 + 8) * N + col] = make_float2(v2, v3);
        }
    }
}

// ---------------- flash attention (causal, fp16 tensor cores) ----------------
// 64-query x 64-key tiles, 128 threads (4 warps), warp w owns rows [16w,16w+16).
// Ksu[d2][key]: packs dims (2d2,2d2+1) of each key.  32 x 72 u32
// Vsu[k2][dim]: packs keys (2k2,2k2+1) at each dim.  32 x 72 u32
// Psu[row][k2]: Q staging then P, packed along key.  64 x 36 u32
#define AQ 64
#define AK 64
#define KP 72
#define PP 36

__global__ __launch_bounds__(128)
void flash_attn_fp16_kernel(float* __restrict__ O) {
    __shared__ unsigned Ksu[(HS / 2) * KP];
    __shared__ unsigned Vsu[(AK / 2) * KP];
    __shared__ unsigned Psu[AQ * PP];

    int qt = gridDim.x - 1 - blockIdx.x;      // longest blocks first
    int h  = blockIdx.y;
    int b  = blockIdx.z;
    int tid = threadIdx.x;
    int warp = tid >> 5, lane = tid & 31;
    int g = lane >> 2, t4 = lane & 3;
    int q0 = qt * AQ;
    int wrow = warp * 16;

    // ---- stage Q tile into Psu (packed along dim) ----
    {
        int row = tid >> 1;
        int c0  = (tid & 1) * 32;
        const float* qp = g_qkv + (size_t)(b * TT + q0 + row) * (3 * DD) + h * HS + c0;
        #pragma unroll
        for (int cc = 0; cc < 32; cc += 4) {
            float4 v = *(const float4*)&qp[cc];
            Psu[row * PP + ((c0 + cc) >> 1)    ] = packh2(v.x, v.y);
            Psu[row * PP + ((c0 + cc) >> 1) + 1] = packh2(v.z, v.w);
        }
    }
    __syncthreads();

    // ---- persistent Q A-fragments: 4 k16-steps ----
    unsigned qa[4][4];
    #pragma unroll
    for (int kk = 0; kk < 4; kk++) {
        qa[kk][0] = Psu[(wrow + g    ) * PP + kk * 8 + t4];
        qa[kk][1] = Psu[(wrow + g + 8) * PP + kk * 8 + t4];
        qa[kk][2] = Psu[(wrow + g    ) * PP + kk * 8 + t4 + 4];
        qa[kk][3] = Psu[(wrow + g + 8) * PP + kk * 8 + t4 + 4];
    }
    __syncthreads();   // Psu free for P

    float oc[8][4];
    #pragma unroll
    for (int nt = 0; nt < 8; nt++)
        #pragma unroll
        for (int q = 0; q < 4; q++) oc[nt][q] = 0.f;
    float m0 = -1e30f, m1 = -1e30f, l0 = 0.f, l1 = 0.f;
    const float scale = rsqrtf((float)DD);

    int ntiles = qt + 1;
    for (int jt = 0; jt < ntiles; jt++) {
        __syncthreads();   // previous tile's MMA reads of Ksu/Vsu complete
        // ---- load K (transposed+packed) ----
        {
            int row = tid >> 1;            // key
            int c0  = (tid & 1) * 32;      // dim start
            const float* kp = g_qkv + (size_t)(b * TT + jt * AK + row) * (3 * DD) + DD + h * HS + c0;
            #pragma unroll
            for (int cc = 0; cc < 32; cc += 4) {
                float4 kv = *(const float4*)&kp[cc];
                Ksu[((c0 + cc) >> 1) * KP + row      ] = packh2(kv.x, kv.y);
                Ksu[(((c0 + cc) >> 1) + 1) * KP + row] = packh2(kv.z, kv.w);
            }
        }
        // ---- load V (packed across key pairs) ----
        {
            #pragma unroll
            for (int i = 0; i < 4; i++) {
                int f = tid + i * 128;     // 0..511
                int k2 = f >> 4;           // key pair 0..31
                int c  = (f & 15) * 4;     // dim
                const float* vp = g_qkv + (size_t)(b * TT + jt * AK + 2 * k2) * (3 * DD) + 2 * DD + h * HS + c;
                float4 va = *(const float4*)vp;
                float4 vb = *(const float4*)(vp + 3 * DD);
                Vsu[k2 * KP + c    ] = packh2(va.x, vb.x);
                Vsu[k2 * KP + c + 1] = packh2(va.y, vb.y);
                Vsu[k2 * KP + c + 2] = packh2(va.z, vb.z);
                Vsu[k2 * KP + c + 3] = packh2(va.w, vb.w);
            }
        }
        __syncthreads();

        // ---- S = Q K^T ----
        float sc[8][4];
        #pragma unroll
        for (int nt = 0; nt < 8; nt++)
            #pragma unroll
            for (int q = 0; q < 4; q++) sc[nt][q] = 0.f;
        #pragma unroll
        for (int kk = 0; kk < 4; kk++) {
            #pragma unroll
            for (int nt = 0; nt < 8; nt++) {
                unsigned bf[2];
                bf[0] = Ksu[(kk * 8 + t4    ) * KP + nt * 8 + g];
                bf[1] = Ksu[(kk * 8 + t4 + 4) * KP + nt * 8 + g];
                mma_fp16(sc[nt], qa[kk], bf);
            }
        }

        // ---- scale + causal mask (diagonal tile only) ----
        if (jt == ntiles - 1) {
            int r0 = wrow + g, r1 = wrow + g + 8;
            #pragma unroll
            for (int nt = 0; nt < 8; nt++) {
                int c0i = nt * 8 + 2 * t4, c1i = c0i + 1;
                sc[nt][0] = (c0i <= r0) ? sc[nt][0] * scale : -1e30f;
                sc[nt][1] = (c1i <= r0) ? sc[nt][1] * scale : -1e30f;
                sc[nt][2] = (c0i <= r1) ? sc[nt][2] * scale : -1e30f;
                sc[nt][3] = (c1i <= r1) ? sc[nt][3] * scale : -1e30f;
            }
        } else {
            #pragma unroll
            for (int nt = 0; nt < 8; nt++)
                #pragma unroll
                for (int q = 0; q < 4; q++) sc[nt][q] *= scale;
        }

        // ---- online softmax (rows g and g+8; reduce over 4 lanes sharing g) ----
        float pm0 = -1e30f, pm1 = -1e30f;
        #pragma unroll
        for (int nt = 0; nt < 8; nt++) {
            pm0 = fmaxf(pm0, fmaxf(sc[nt][0], sc[nt][1]));
            pm1 = fmaxf(pm1, fmaxf(sc[nt][2], sc[nt][3]));
        }
        #pragma unroll
        for (int ofs = 1; ofs < 4; ofs <<= 1) {
            pm0 = fmaxf(pm0, __shfl_xor_sync(0xffffffffu, pm0, ofs, 4));
            pm1 = fmaxf(pm1, __shfl_xor_sync(0xffffffffu, pm1, ofs, 4));
        }
        float mn0 = fmaxf(m0, pm0), mn1 = fmaxf(m1, pm1);
        float corr0 = __expf(m0 - mn0), corr1 = __expf(m1 - mn1);
        m0 = mn0; m1 = mn1;
        l0 *= corr0; l1 *= corr1;
        #pragma unroll
        for (int nt = 0; nt < 8; nt++) {
            oc[nt][0] *= corr0; oc[nt][1] *= corr0;
            oc[nt][2] *= corr1; oc[nt][3] *= corr1;
        }
        // exponentiate + write P packed (cols 2t4,2t4+1 are one pair)
        #pragma unroll
        for (int nt = 0; nt < 8; nt++) {
            float p0 = __expf(sc[nt][0] - m0);
            float p1 = __expf(sc[nt][1] - m0);
            float p2 = __expf(sc[nt][2] - m1);
            float p3 = __expf(sc[nt][3] - m1);
            l0 += p0 + p1; l1 += p2 + p3;
            Psu[(wrow + g    ) * PP + nt * 4 + t4] = packh2(p0, p1);
            Psu[(wrow + g + 8) * PP + nt * 4 + t4] = packh2(p2, p3);
        }
        __syncwarp();

        // ---- O += P V ----
        #pragma unroll
        for (int kk = 0; kk < 4; kk++) {
            unsigned pa[4];
            pa[0] = Psu[(wrow + g    ) * PP + kk * 8 + t4];
            pa[1] = Psu[(wrow + g + 8) * PP + kk * 8 + t4];
            pa[2] = Psu[(wrow + g    ) * PP + kk * 8 + t4 + 4];
            pa[3] = Psu[(wrow + g + 8) * PP + kk * 8 + t4 + 4];
            #pragma unroll
            for (int nt = 0; nt < 8; nt++) {
                unsigned bf[2];
                bf[0] = Vsu[(kk * 8 + t4    ) * KP + nt * 8 + g];
                bf[1] = Vsu[(kk * 8 + t4 + 4) * KP + nt * 8 + g];
                mma_fp16(oc[nt], pa, bf);
            }
        }
        __syncwarp();   // P reads done before next tile's stores
    }

    // ---- epilogue ----
    #pragma unroll
    for (int ofs = 1; ofs < 4; ofs <<= 1) {
        l0 += __shfl_xor_sync(0xffffffffu, l0, ofs, 4);
        l1 += __shfl_xor_sync(0xffffffffu, l1, ofs, 4);
    }
    float inv0 = 1.0f / l0, inv1 = 1.0f / l1;
    #pragma unroll
    for (int nt = 0; nt < 8; nt++) {
        int col = h * HS + nt * 8 + 2 * t4;
        size_t r0 = (size_t)(b * TT + q0 + wrow + g) * DD;
        size_t r1 = (size_t)(b * TT + q0 + wrow + g + 8) * DD;
        *(float2*)&O[r0 + col] = make_float2(oc[nt][0] * inv0, oc[nt][1] * inv0);
        *(float2*)&O[r1 + col] = make_float2(oc[nt][2] * inv1, oc[nt][3] * inv1);
    }
}

// ---------------- SwiGLU elementwise ----------------
__global__ void swiglu_kernel() {
    int idx = blockIdx.x * 256 + threadIdx.x;
    if (idx >= ROWS * HALF) return;
    int row = idx / HALF, col = idx % HALF;
    float a = g_u[(size_t)row * FF + col];
    float z = g_u[(size_t)row * FF + HALF + col];
    float sig = 1.0f / (1.0f + __expf(-z));
    g_gsw[idx] = z * sig * a;
}

// ---------------- launch ----------------
extern "C" void kernel_launch(void* const* d_in, const int* in_sizes, int n_in,
                              void* d_out, int out_size) {
    const float* x  = (const float*)d_in[0];
    const float* Wq = (const float*)d_in[1];
    const float* Wk = (const float*)d_in[2];
    const float* Wv = (const float*)d_in[3];
    const float* Wo = (const float*)d_in[4];
    const float* bo = (const float*)d_in[5];
    const float* W1 = (const float*)d_in[6];
    const float* b1 = (const float*)d_in[7];
    const float* W2 = (const float*)d_in[8];
    const float* b2 = (const float*)d_in[9];
    const float* g1 = (const float*)d_in[10];
    const float* g2 = (const float*)d_in[11];
    float* out = (float*)d_out;

    float *p_h, *p_wqkv, *p_qkv, *p_attn, *p_x1, *p_u, *p_gsw;
    cudaGetSymbolAddress((void**)&p_h,    g_h);
    cudaGetSymbolAddress((void**)&p_wqkv, g_wqkv);
    cudaGetSymbolAddress((void**)&p_qkv,  g_qkv);
    cudaGetSymbolAddress((void**)&p_attn, g_attn);
    cudaGetSymbolAddress((void**)&p_x1,   g_x1);
    cudaGetSymbolAddress((void**)&p_u,    g_u);
    cudaGetSymbolAddress((void**)&p_gsw,  g_gsw);

    // 1. pack QKV weights
    pack_wqkv_kernel<<<(DD * 3 * DD + 255) / 256, 256>>>(Wq, Wk, Wv);
    // 2. rmsnorm(x, g1) -> h
    rmsnorm_kernel<<<ROWS, 256>>>(x, g1, p_h);
    // 3. QKV = h @ Wqkv   [4096 x 2304]
    gemm_fp16_kernel<<<dim3((3 * DD) / GBN, ROWS / GBM), 256>>>(
        p_h, p_wqkv, p_qkv, nullptr, nullptr, ROWS, 3 * DD, DD);
    // 4. flash attention (fp16 tensor cores) -> attn
    flash_attn_fp16_kernel<<<dim3(TT / AQ, HH, BB), 128>>>(p_attn);
    // 5. x1 = x + attn @ Wo + bo
    gemm_fp16_kernel<<<dim3(DD / GBN, ROWS / GBM), 256>>>(
        p_attn, Wo, p_x1, bo, x, ROWS, DD, DD);
    // 6. rmsnorm(x1, g2) -> h (reuse)
    rmsnorm_kernel<<<ROWS, 256>>>(p_x1, g2, p_h);
    // 7. u = h @ W1 + b1   [4096 x 3072]
    gemm_fp16_kernel<<<dim3(FF / GBN, ROWS / GBM), 256>>>(
        p_h, W1, p_u, b1, nullptr, ROWS, FF, DD);
    // 8. swiglu: gsw = silu(gate) * a
    swiglu_kernel<<<(ROWS * HALF + 255) / 256, 256>>>();
    // 9. out = x1 + gsw @ W2 + b2
    gemm_fp16_kernel<<<dim3(DD / GBN, ROWS / GBM), 256>>>(
        p_gsw, W2, out, b2, p_x1, ROWS, DD, HALF);
}

// round 14
// speedup vs baseline: 5.1680x; 1.3023x over previous
#include <cuda_runtime.h>
#include <cuda_fp16.h>
#include <cstdint>

// Problem constants
#define BB 2
#define TT 2048
#define DD 768
#define HH 12
#define HS 64
#define FF 3072
#define HALF 1536
#define ROWS (BB*TT)          // 4096

// ---------------- device scratch (no allocations allowed) ----------------
__device__ __half g_hh   [ROWS * DD];      // rmsnorm output (half, reused for h2)
__device__ float  g_qkv  [ROWS * 3 * DD];  // Q|K|V  [4096][2304] (float, for flash)
__device__ __half g_attnh[ROWS * DD];      // attention output (half)
__device__ float  g_x1   [ROWS * DD];      // x + attn proj residual
__device__ float  g_u    [ROWS * FF];      // FFN hidden
__device__ __half g_gswh [ROWS * HALF];    // silu(gate)*a (half)
__device__ __half g_wqkvT[3 * DD * DD];    // [2304][768]  (B^T, half)
__device__ __half g_woT  [DD * DD];        // [768][768]
__device__ __half g_w1T  [FF * DD];        // [3072][768]
__device__ __half g_w2T  [DD * HALF];      // [768][1536]

// ---------------- helpers ----------------
__device__ __forceinline__ unsigned packh2(float lo, float hi) {
    __half2 h = __floats2half2_rn(lo, hi);
    return *reinterpret_cast<unsigned*>(&h);
}
__device__ __forceinline__ void mma_fp16(float c[4], const unsigned a[4], const unsigned b[2]) {
    asm volatile(
        "mma.sync.aligned.m16n8k16.row.col.f32.f16.f16.f32 "
        "{%0,%1,%2,%3}, {%4,%5,%6,%7}, {%8,%9}, {%0,%1,%2,%3};"
        : "+f"(c[0]), "+f"(c[1]), "+f"(c[2]), "+f"(c[3])
        : "r"(a[0]), "r"(a[1]), "r"(a[2]), "r"(a[3]), "r"(b[0]), "r"(b[1]));
}
__device__ __forceinline__ uint32_t cvta_smem(const void* p) {
    uint32_t a;
    asm("{ .reg .u64 t; cvta.to.shared.u64 t, %1; cvt.u32.u64 %0, t; }" : "=r"(a) : "l"(p));
    return a;
}
#define CP_ASYNC16(dst, src) asm volatile("cp.async.cg.shared.global [%0], [%1], 16;" :: "r"(dst), "l"(src))
#define CP_COMMIT()          asm volatile("cp.async.commit_group;" ::: "memory")
#define CP_WAIT0()           asm volatile("cp.async.wait_group 0;" ::: "memory")
#define CP_WAIT1()           asm volatile("cp.async.wait_group 1;" ::: "memory")

// ---------------- tiled transpose float -> half: dst[C][R] = src[R][C]^T -------
__global__ void transpose_f2h(const float* __restrict__ src, __half* __restrict__ dst,
                              int R, int C, size_t src_mat_stride, size_t dst_mat_stride) {
    __shared__ float t[32][33];
    src += blockIdx.z * src_mat_stride;
    dst += blockIdx.z * dst_mat_stride;
    int x = blockIdx.x * 32 + threadIdx.x;
    #pragma unroll
    for (int j = threadIdx.y; j < 32; j += 8) {
        int y = blockIdx.y * 32 + j;
        if (y < R && x < C) t[j][threadIdx.x] = src[(size_t)y * C + x];
    }
    __syncthreads();
    int xx = blockIdx.y * 32 + threadIdx.x;
    #pragma unroll
    for (int j = threadIdx.y; j < 32; j += 8) {
        int yy = blockIdx.x * 32 + j;
        if (yy < C && xx < R) dst[(size_t)yy * R + xx] = __float2half(t[threadIdx.x][j]);
    }
}

// ---------------- RMSNorm: y = g * x / (rms + eps), half out ----------------
__global__ void rmsnorm_kernel(const float* __restrict__ X,
                               const float* __restrict__ g,
                               __half* __restrict__ Y) {
    int row = blockIdx.x;
    const float* x = X + (size_t)row * DD;
    __half* y = Y + (size_t)row * DD;
    __shared__ float red[256];
    int t = threadIdx.x;
    float ss = 0.f;
    #pragma unroll
    for (int i = t; i < DD; i += 256) { float v = x[i]; ss += v * v; }
    red[t] = ss; __syncthreads();
    #pragma unroll
    for (int s2 = 128; s2 > 0; s2 >>= 1) {
        if (t < s2) red[t] += red[t + s2];
        __syncthreads();
    }
    float rms = sqrtf(red[0] * (1.0f / DD));
    float inv = 1.0f / (rms + 1e-8f);
    #pragma unroll
    for (int i = t; i < DD; i += 256) y[i] = __float2half(g[i] * x[i] * inv);
}

// ---- fp16 mma.sync GEMM, cp.async double-buffered: C = A[M,K]h @ BT[N,K]h^T --
// BM=BN=128, BK=32. 8 warps, warp tile 32x64 (2x8 m16n8k16 frags, 2 k-steps).
// smem tiles as u32 (half2 pairs along k): 128 rows x 16 kpairs, pitch 20 u32.
#define GBK 32
#define TP 20                 // u32 pitch (16 + 4 pad): frag LDS conflict-free
#define TSZ (128 * TP)        // u32 per buffer

__global__ __launch_bounds__(256)
void gemm_fp16_kernel(const __half* __restrict__ A, const __half* __restrict__ BT,
                      float* __restrict__ C,
                      const float* __restrict__ bias, const float* __restrict__ res,
                      int M, int N, int K) {
    __shared__ unsigned sA[2 * TSZ];
    __shared__ unsigned sB[2 * TSZ];

    int tid  = threadIdx.x;
    int warp = tid >> 5;
    int lane = tid & 31;
    int g  = lane >> 2;
    int t4 = lane & 3;
    int wm = (warp >> 1) * 32;
    int wn = (warp & 1) * 64;
    int block_row = blockIdx.y * 128;
    int block_col = blockIdx.x * 128;

    const __half* Ag = A + (size_t)block_row * K;
    const __half* Bg = BT + (size_t)block_col * K;
    uint32_t aSA = cvta_smem(sA);
    uint32_t aSB = cvta_smem(sB);

    int lrow = tid >> 2;      // 0..63 (two rows per thread via i-loop)
    int lq   = tid & 3;       // uint4 slot (8 halves)

    float c[2][8][4];
    #pragma unroll
    for (int mt = 0; mt < 2; mt++)
        #pragma unroll
        for (int nt = 0; nt < 8; nt++)
            #pragma unroll
            for (int q = 0; q < 4; q++) c[mt][nt][q] = 0.f;

    int NC = K / GBK;

    // prologue: load chunk 0 into buffer 0
    #pragma unroll
    for (int i = 0; i < 2; i++) {
        int row = lrow + i * 64;
        uint32_t off = (uint32_t)(row * TP + lq * 4) * 4;
        CP_ASYNC16(aSA + off, Ag + (size_t)row * K + lq * 8);
        CP_ASYNC16(aSB + off, Bg + (size_t)row * K + lq * 8);
    }
    CP_COMMIT();

    for (int ck = 0; ck < NC; ck++) {
        int buf = ck & 1;
        if (ck + 1 < NC) {
            int nbuf = buf ^ 1;
            const __half* Agc = Ag + (ck + 1) * GBK;
            const __half* Bgc = Bg + (ck + 1) * GBK;
            #pragma unroll
            for (int i = 0; i < 2; i++) {
                int row = lrow + i * 64;
                uint32_t off = (uint32_t)(nbuf * TSZ + row * TP + lq * 4) * 4;
                CP_ASYNC16(aSA + off, Agc + (size_t)row * K + lq * 8);
                CP_ASYNC16(aSB + off, Bgc + (size_t)row * K + lq * 8);
            }
            CP_COMMIT();
            CP_WAIT1();
        } else {
            CP_WAIT0();
        }
        __syncthreads();

        const unsigned* As = sA + buf * TSZ;
        const unsigned* Bs = sB + buf * TSZ;
        #pragma unroll
        for (int kk = 0; kk < 2; kk++) {
            unsigned a[2][4];
            #pragma unroll
            for (int mt = 0; mt < 2; mt++) {
                int r0 = wm + mt * 16 + g;
                a[mt][0] = As[(r0    ) * TP + kk * 8 + t4];
                a[mt][1] = As[(r0 + 8) * TP + kk * 8 + t4];
                a[mt][2] = As[(r0    ) * TP + kk * 8 + t4 + 4];
                a[mt][3] = As[(r0 + 8) * TP + kk * 8 + t4 + 4];
            }
            unsigned b[8][2];
            #pragma unroll
            for (int nt = 0; nt < 8; nt++) {
                int cn = wn + nt * 8 + g;
                b[nt][0] = Bs[cn * TP + kk * 8 + t4];
                b[nt][1] = Bs[cn * TP + kk * 8 + t4 + 4];
            }
            #pragma unroll
            for (int mt = 0; mt < 2; mt++)
                #pragma unroll
                for (int nt = 0; nt < 8; nt++)
                    mma_fp16(c[mt][nt], a[mt], b[nt]);
        }
        __syncthreads();   // done reading buf before it is refilled at ck+2
    }

    #pragma unroll
    for (int mt = 0; mt < 2; mt++) {
        int r0 = block_row + wm + mt * 16 + g;
        #pragma unroll
        for (int nt = 0; nt < 8; nt++) {
            int col = block_col + wn + nt * 8 + t4 * 2;
            float v0 = c[mt][nt][0], v1 = c[mt][nt][1];
            float v2 = c[mt][nt][2], v3 = c[mt][nt][3];
            if (bias) {
                float b0 = bias[col], b1 = bias[col + 1];
                v0 += b0; v1 += b1; v2 += b0; v3 += b1;
            }
            if (res) {
                v0 += res[(size_t)r0 * N + col];
                v1 += res[(size_t)r0 * N + col + 1];
                v2 += res[(size_t)(r0 + 8) * N + col];
                v3 += res[(size_t)(r0 + 8) * N + col + 1];
            }
            *(float2*)&C[(size_t)r0 * N + col]       = make_float2(v0, v1);
            *(float2*)&C[(size_t)(r0 + 8) * N + col] = make_float2(v2, v3);
        }
    }
}

// ---------------- flash attention (causal, fp16 mma.sync) ----------------
// Q/K/V in g_qkv float rows [b*T+t][2304] at col offsets 0 / 768 / 1536 (+h*64)
#define AQ 64
#define AK 64
#define KP 72
#define PP 36

__global__ __launch_bounds__(128)
void flash_attn_fp16_kernel(__half* __restrict__ O) {
    __shared__ unsigned Ksu[(HS / 2) * KP];
    __shared__ unsigned Vsu[(AK / 2) * KP];
    __shared__ unsigned Psu[AQ * PP];

    int qt = gridDim.x - 1 - blockIdx.x;      // longest blocks first
    int h  = blockIdx.y;
    int b  = blockIdx.z;
    int tid = threadIdx.x;
    int warp = tid >> 5, lane = tid & 31;
    int g = lane >> 2, t4 = lane & 3;
    int q0 = qt * AQ;
    int wrow = warp * 16;

    // stage Q tile into Psu (packed along dim)
    {
        int row = tid >> 1;
        int c0  = (tid & 1) * 32;
        const float* qp = g_qkv + (size_t)(b * TT + q0 + row) * (3 * DD) + h * HS + c0;
        #pragma unroll
        for (int cc = 0; cc < 32; cc += 4) {
            float4 v = *(const float4*)&qp[cc];
            Psu[row * PP + ((c0 + cc) >> 1)    ] = packh2(v.x, v.y);
            Psu[row * PP + ((c0 + cc) >> 1) + 1] = packh2(v.z, v.w);
        }
    }
    __syncthreads();

    unsigned qa[4][4];
    #pragma unroll
    for (int kk = 0; kk < 4; kk++) {
        qa[kk][0] = Psu[(wrow + g    ) * PP + kk * 8 + t4];
        qa[kk][1] = Psu[(wrow + g + 8) * PP + kk * 8 + t4];
        qa[kk][2] = Psu[(wrow + g    ) * PP + kk * 8 + t4 + 4];
        qa[kk][3] = Psu[(wrow + g + 8) * PP + kk * 8 + t4 + 4];
    }
    __syncthreads();

    float oc[8][4];
    #pragma unroll
    for (int nt = 0; nt < 8; nt++)
        #pragma unroll
        for (int q = 0; q < 4; q++) oc[nt][q] = 0.f;
    float m0 = -1e30f, m1 = -1e30f, l0 = 0.f, l1 = 0.f;
    const float scale = rsqrtf((float)DD);

    int ntiles = qt + 1;
    for (int jt = 0; jt < ntiles; jt++) {
        __syncthreads();
        {
            int row = tid >> 1;
            int c0  = (tid & 1) * 32;
            const float* kp = g_qkv + (size_t)(b * TT + jt * AK + row) * (3 * DD) + DD + h * HS + c0;
            #pragma unroll
            for (int cc = 0; cc < 32; cc += 4) {
                float4 kv = *(const float4*)&kp[cc];
                Ksu[((c0 + cc) >> 1) * KP + row      ] = packh2(kv.x, kv.y);
                Ksu[(((c0 + cc) >> 1) + 1) * KP + row] = packh2(kv.z, kv.w);
            }
        }
        {
            #pragma unroll
            for (int i = 0; i < 4; i++) {
                int f = tid + i * 128;
                int k2 = f >> 4;
                int c  = (f & 15) * 4;
                const float* vp = g_qkv + (size_t)(b * TT + jt * AK + 2 * k2) * (3 * DD) + 2 * DD + h * HS + c;
                float4 va = *(const float4*)vp;
                float4 vb = *(const float4*)(vp + 3 * DD);
                Vsu[k2 * KP + c    ] = packh2(va.x, vb.x);
                Vsu[k2 * KP + c + 1] = packh2(va.y, vb.y);
                Vsu[k2 * KP + c + 2] = packh2(va.z, vb.z);
                Vsu[k2 * KP + c + 3] = packh2(va.w, vb.w);
            }
        }
        __syncthreads();

        float sc[8][4];
        #pragma unroll
        for (int nt = 0; nt < 8; nt++)
            #pragma unroll
            for (int q = 0; q < 4; q++) sc[nt][q] = 0.f;
        #pragma unroll
        for (int kk = 0; kk < 4; kk++) {
            #pragma unroll
            for (int nt = 0; nt < 8; nt++) {
                unsigned bf[2];
                bf[0] = Ksu[(kk * 8 + t4    ) * KP + nt * 8 + g];
                bf[1] = Ksu[(kk * 8 + t4 + 4) * KP + nt * 8 + g];
                mma_fp16(sc[nt], qa[kk], bf);
            }
        }

        if (jt == ntiles - 1) {
            int r0 = wrow + g, r1 = wrow + g + 8;
            #pragma unroll
            for (int nt = 0; nt < 8; nt++) {
                int c0i = nt * 8 + 2 * t4, c1i = c0i + 1;
                sc[nt][0] = (c0i <= r0) ? sc[nt][0] * scale : -1e30f;
                sc[nt][1] = (c1i <= r0) ? sc[nt][1] * scale : -1e30f;
                sc[nt][2] = (c0i <= r1) ? sc[nt][2] * scale : -1e30f;
                sc[nt][3] = (c1i <= r1) ? sc[nt][3] * scale : -1e30f;
            }
        } else {
            #pragma unroll
            for (int nt = 0; nt < 8; nt++)
                #pragma unroll
                for (int q = 0; q < 4; q++) sc[nt][q] *= scale;
        }

        float pm0 = -1e30f, pm1 = -1e30f;
        #pragma unroll
        for (int nt = 0; nt < 8; nt++) {
            pm0 = fmaxf(pm0, fmaxf(sc[nt][0], sc[nt][1]));
            pm1 = fmaxf(pm1, fmaxf(sc[nt][2], sc[nt][3]));
        }
        #pragma unroll
        for (int ofs = 1; ofs < 4; ofs <<= 1) {
            pm0 = fmaxf(pm0, __shfl_xor_sync(0xffffffffu, pm0, ofs, 4));
            pm1 = fmaxf(pm1, __shfl_xor_sync(0xffffffffu, pm1, ofs, 4));
        }
        float mn0 = fmaxf(m0, pm0), mn1 = fmaxf(m1, pm1);
        float corr0 = __expf(m0 - mn0), corr1 = __expf(m1 - mn1);
        m0 = mn0; m1 = mn1;
        l0 *= corr0; l1 *= corr1;
        #pragma unroll
        for (int nt = 0; nt < 8; nt++) {
            oc[nt][0] *= corr0; oc[nt][1] *= corr0;
            oc[nt][2] *= corr1; oc[nt][3] *= corr1;
        }
        #pragma unroll
        for (int nt = 0; nt < 8; nt++) {
            float p0 = __expf(sc[nt][0] - m0);
            float p1 = __expf(sc[nt][1] - m0);
            float p2 = __expf(sc[nt][2] - m1);
            float p3 = __expf(sc[nt][3] - m1);
            l0 += p0 + p1; l1 += p2 + p3;
            Psu[(wrow + g    ) * PP + nt * 4 + t4] = packh2(p0, p1);
            Psu[(wrow + g + 8) * PP + nt * 4 + t4] = packh2(p2, p3);
        }
        __syncwarp();

        #pragma unroll
        for (int kk = 0; kk < 4; kk++) {
            unsigned pa[4];
            pa[0] = Psu[(wrow + g    ) * PP + kk * 8 + t4];
            pa[1] = Psu[(wrow + g + 8) * PP + kk * 8 + t4];
            pa[2] = Psu[(wrow + g    ) * PP + kk * 8 + t4 + 4];
            pa[3] = Psu[(wrow + g + 8) * PP + kk * 8 + t4 + 4];
            #pragma unroll
            for (int nt = 0; nt < 8; nt++) {
                unsigned bf[2];
                bf[0] = Vsu[(kk * 8 + t4    ) * KP + nt * 8 + g];
                bf[1] = Vsu[(kk * 8 + t4 + 4) * KP + nt * 8 + g];
                mma_fp16(oc[nt], pa, bf);
            }
        }
        __syncwarp();
    }

    #pragma unroll
    for (int ofs = 1; ofs < 4; ofs <<= 1) {
        l0 += __shfl_xor_sync(0xffffffffu, l0, ofs, 4);
        l1 += __shfl_xor_sync(0xffffffffu, l1, ofs, 4);
    }
    float inv0 = 1.0f / l0, inv1 = 1.0f / l1;
    #pragma unroll
    for (int nt = 0; nt < 8; nt++) {
        int col = h * HS + nt * 8 + 2 * t4;
        size_t r0 = (size_t)(b * TT + q0 + wrow + g) * DD;
        size_t r1 = (size_t)(b * TT + q0 + wrow + g + 8) * DD;
        *(__half2*)&O[r0 + col] = __floats2half2_rn(oc[nt][0] * inv0, oc[nt][1] * inv0);
        *(__half2*)&O[r1 + col] = __floats2half2_rn(oc[nt][2] * inv1, oc[nt][3] * inv1);
    }
}

// ---------------- SwiGLU elementwise (float in, half out) ----------------
__global__ void swiglu_kernel() {
    int idx = blockIdx.x * 256 + threadIdx.x;
    if (idx >= ROWS * HALF) return;
    int row = idx / HALF, col = idx % HALF;
    float a = g_u[(size_t)row * FF + col];
    float z = g_u[(size_t)row * FF + HALF + col];
    float sig = 1.0f / (1.0f + __expf(-z));
    g_gswh[idx] = __float2half(z * sig * a);
}

// ---------------- launch ----------------
extern "C" void kernel_launch(void* const* d_in, const int* in_sizes, int n_in,
                              void* d_out, int out_size) {
    const float* x  = (const float*)d_in[0];
    const float* Wq = (const float*)d_in[1];
    const float* Wk = (const float*)d_in[2];
    const float* Wv = (const float*)d_in[3];
    const float* Wo = (const float*)d_in[4];
    const float* bo = (const float*)d_in[5];
    const float* W1 = (const float*)d_in[6];
    const float* b1 = (const float*)d_in[7];
    const float* W2 = (const float*)d_in[8];
    const float* b2 = (const float*)d_in[9];
    const float* g1 = (const float*)d_in[10];
    const float* g2 = (const float*)d_in[11];
    float* out = (float*)d_out;

    __half *p_hh, *p_attnh, *p_gswh, *p_wqkvT, *p_woT, *p_w1T, *p_w2T;
    float *p_qkv, *p_x1, *p_u;
    cudaGetSymbolAddress((void**)&p_hh,    g_hh);
    cudaGetSymbolAddress((void**)&p_qkv,   g_qkv);
    cudaGetSymbolAddress((void**)&p_attnh, g_attnh);
    cudaGetSymbolAddress((void**)&p_x1,    g_x1);
    cudaGetSymbolAddress((void**)&p_u,     g_u);
    cudaGetSymbolAddress((void**)&p_gswh,  g_gswh);
    cudaGetSymbolAddress((void**)&p_wqkvT, g_wqkvT);
    cudaGetSymbolAddress((void**)&p_woT,   g_woT);
    cudaGetSymbolAddress((void**)&p_w1T,   g_w1T);
    cudaGetSymbolAddress((void**)&p_w2T,   g_w2T);

    dim3 tb(32, 8);
    // weight transposes -> half [N][K]
    transpose_f2h<<<dim3(2, 24, HH), tb>>>(Wq, p_wqkvT,               DD, HS, (size_t)DD * HS, (size_t)HS * DD);
    transpose_f2h<<<dim3(2, 24, HH), tb>>>(Wk, p_wqkvT + DD * DD,     DD, HS, (size_t)DD * HS, (size_t)HS * DD);
    transpose_f2h<<<dim3(2, 24, HH), tb>>>(Wv, p_wqkvT + 2 * DD * DD, DD, HS, (size_t)DD * HS, (size_t)HS * DD);
    transpose_f2h<<<dim3(24, 24, 1), tb>>>(Wo, p_woT, DD, DD, 0, 0);
    transpose_f2h<<<dim3(96, 24, 1), tb>>>(W1, p_w1T, DD, FF, 0, 0);
    transpose_f2h<<<dim3(24, 48, 1), tb>>>(W2, p_w2T, HALF, DD, 0, 0);

    // rmsnorm(x, g1) -> hh (half)
    rmsnorm_kernel<<<ROWS, 256>>>(x, g1, p_hh);
    // QKV = hh @ WqkvT^T   [4096 x 2304]
    gemm_fp16_kernel<<<dim3(3 * DD / 128, ROWS / 128), 256>>>(
        p_hh, p_wqkvT, p_qkv, nullptr, nullptr, ROWS, 3 * DD, DD);
    // flash attention -> attnh (half)
    flash_attn_fp16_kernel<<<dim3(TT / AQ, HH, BB), 128>>>(p_attnh);
    // x1 = x + attn @ Wo + bo
    gemm_fp16_kernel<<<dim3(DD / 128, ROWS / 128), 256>>>(
        p_attnh, p_woT, p_x1, bo, x, ROWS, DD, DD);
    // rmsnorm(x1, g2) -> hh
    rmsnorm_kernel<<<ROWS, 256>>>(p_x1, g2, p_hh);
    // u = hh @ W1 + b1
    gemm_fp16_kernel<<<dim3(FF / 128, ROWS / 128), 256>>>(
        p_hh, p_w1T, p_u, b1, nullptr, ROWS, FF, DD);
    // swiglu
    swiglu_kernel<<<(ROWS * HALF + 255) / 256, 256>>>();
    // out = x1 + gsw @ W2 + b2
    gemm_fp16_kernel<<<dim3(DD / 128, ROWS / 128), 256>>>(
        p_gswh, p_w2T, out, b2, p_x1, ROWS, DD, HALF);
}